// round 3
// baseline (speedup 1.0000x reference)
#include <cuda_runtime.h>
#include <cuda_bf16.h>

#define BATCH 2
#define H 512
#define W 512
#define INF_SQ 1e12f

// Scratch: squared horizontal distance to nearest fg / bg pixel (row pass output).
__device__ float g_neg_buf[BATCH * H * W];  // nearest mask==1 pixel along the row
__device__ float g_pos_buf[BATCH * H * W];  // nearest mask==0 pixel along the row

// -------- Row pass: one block per row, one thread per pixel. --------
// Outward search from each pixel for the nearest pixel of each class.
// Exact: first hit at offset o gives horizontal distance o.
__global__ void __launch_bounds__(W) row_pass(const float* __restrict__ mask) {
    __shared__ unsigned char m[W];
    const int row = blockIdx.x;          // 0 .. BATCH*H-1
    const int i   = threadIdx.x;

    m[i] = (mask[row * W + i] == 1.0f) ? 1 : 0;
    __syncthreads();

    int dfg = -1, dbg = -1;
    for (int o = 0; o < W; ++o) {
        if (dfg >= 0 && dbg >= 0) break;
        const int l = i - o, r = i + o;
        bool hitT = false, hitF = false;
        if (l >= 0) { if (m[l]) hitT = true; else hitF = true; }
        if (r < W)  { if (m[r]) hitT = true; else hitF = true; }
        if (dfg < 0 && hitT) dfg = o;
        if (dbg < 0 && hitF) dbg = o;
    }

    const float fo = (float)dfg, bo = (float)dbg;
    g_neg_buf[row * W + i] = (dfg < 0) ? INF_SQ : fo * fo;
    g_pos_buf[row * W + i] = (dbg < 0) ? INF_SQ : bo * bo;
}

// -------- Column pass: tile of TB_C columns x full H rows in smem. --------
// D[i] = min_k g[k] + (i-k)^2. Since g >= 0, searching outward and stopping
// once o^2 >= best is exact. Combine both fields and emit sqrt(neg)-sqrt(pos).
#define TB_C 8
#define CP_THREADS 256
__global__ void __launch_bounds__(CP_THREADS) col_pass(float* __restrict__ out) {
    __shared__ float sn[H * TB_C];
    __shared__ float sp[H * TB_C];

    const int b  = blockIdx.y;
    const int c0 = blockIdx.x * TB_C;
    const float* __restrict__ gn = g_neg_buf + b * H * W;
    const float* __restrict__ gp = g_pos_buf + b * H * W;

    // Load tile (columns c0..c0+TB_C-1, all H rows) into shared memory.
    for (int idx = threadIdx.x; idx < H * TB_C; idx += CP_THREADS) {
        const int k  = idx / TB_C;
        const int cc = idx - k * TB_C;
        sn[idx] = gn[k * W + c0 + cc];
        sp[idx] = gp[k * W + c0 + cc];
    }
    __syncthreads();

    for (int pix = threadIdx.x; pix < H * TB_C; pix += CP_THREADS) {
        const int i  = pix / TB_C;
        const int cc = pix - i * TB_C;

        float bn = sn[pix];   // candidate k == i (o = 0)
        float bp = sp[pix];

        for (int o = 1; o < H; ++o) {
            const float o2 = (float)(o * o);
            if (o2 >= bn && o2 >= bp) break;   // no further candidate can win
            const int ku = i - o, kd = i + o;
            if (ku >= 0) {
                bn = fminf(bn, sn[ku * TB_C + cc] + o2);
                bp = fminf(bp, sp[ku * TB_C + cc] + o2);
            }
            if (kd < H) {
                bn = fminf(bn, sn[kd * TB_C + cc] + o2);
                bp = fminf(bp, sp[kd * TB_C + cc] + o2);
            }
        }

        out[(b * H + i) * W + c0 + cc] = sqrtf(bn) - sqrtf(bp);
    }
}

extern "C" void kernel_launch(void* const* d_in, const int* in_sizes, int n_in,
                              void* d_out, int out_size) {
    const float* mask = (const float*)d_in[0];
    float* out = (float*)d_out;

    row_pass<<<BATCH * H, W>>>(mask);

    dim3 grid(W / TB_C, BATCH);
    col_pass<<<grid, CP_THREADS>>>(out);
}

// round 4
// speedup vs baseline: 1.6375x; 1.6375x over previous
#include <cuda_runtime.h>
#include <cuda_bf16.h>

#define BATCH 2
#define H 512
#define W 512
#define INF_SQ 1e12f

// Row-pass output, packed: .x = dist^2 to nearest fg (mask==1) in the row,
//                          .y = dist^2 to nearest bg (mask==0) in the row.
__device__ float2 g_row[BATCH * H * W];

// -------- Row pass: one block per row, one thread per pixel. --------
__global__ void __launch_bounds__(W) row_pass(const float* __restrict__ mask) {
    __shared__ unsigned char m[W];
    const int row = blockIdx.x;          // 0 .. BATCH*H-1
    const int i   = threadIdx.x;

    m[i] = (mask[row * W + i] == 1.0f) ? 1 : 0;
    __syncthreads();

    int dfg = -1, dbg = -1;
    for (int o = 0; o < W; ++o) {
        if (dfg >= 0 && dbg >= 0) break;
        const int l = i - o, r = i + o;
        bool hitT = false, hitF = false;
        if (l >= 0) { if (m[l]) hitT = true; else hitF = true; }
        if (r < W)  { if (m[r]) hitT = true; else hitF = true; }
        if (dfg < 0 && hitT) dfg = o;
        if (dbg < 0 && hitF) dbg = o;
    }

    const float fo = (float)dfg, bo = (float)dbg;
    g_row[row * W + i] = make_float2((dfg < 0) ? INF_SQ : fo * fo,
                                     (dbg < 0) ? INF_SQ : bo * bo);
}

// -------- Column pass: one thread per output pixel. --------
// D[i] = min_k g[k] + (i-k)^2. Outward search with early exit at
// o^2 >= current best (exact since g >= 0). Index clamping is exact:
// the clamped candidate g[0] + o^2 (o > i) is >= the true candidate
// g[0] + i^2 which was already folded in at o == i.
#define CP_THREADS 256
__global__ void __launch_bounds__(CP_THREADS) col_pass(float* __restrict__ out) {
    const int idx = blockIdx.x * CP_THREADS + threadIdx.x;  // 0 .. BATCH*H*W-1
    const int c   = idx & (W - 1);
    const int t   = idx >> 9;            // W == 512
    const int i   = t & (H - 1);
    const int b   = t >> 9;              // H == 512

    const float2* __restrict__ g = g_row + b * H * W;

    const float2 own = g[i * W + c];
    float bn = own.x;
    float bp = own.y;

    #pragma unroll 1
    for (int o = 1; o < H; ++o) {
        const float o2 = (float)(o * o);
        if (o2 >= bn && o2 >= bp) break;
        int ku = i - o; ku = (ku < 0) ? 0 : ku;
        int kd = i + o; kd = (kd >= H) ? H - 1 : kd;
        const float2 u = g[ku * W + c];
        const float2 d = g[kd * W + c];
        bn = fminf(bn, fminf(u.x, d.x) + o2);
        bp = fminf(bp, fminf(u.y, d.y) + o2);
    }

    out[idx] = sqrtf(bn) - sqrtf(bp);
}

extern "C" void kernel_launch(void* const* d_in, const int* in_sizes, int n_in,
                              void* d_out, int out_size) {
    const float* mask = (const float*)d_in[0];
    float* out = (float*)d_out;

    row_pass<<<BATCH * H, W>>>(mask);
    col_pass<<<(BATCH * H * W) / CP_THREADS, CP_THREADS>>>(out);
}

// round 9
// speedup vs baseline: 1.9552x; 1.1940x over previous
#include <cuda_runtime.h>
#include <cuda_bf16.h>
#include <cstdint>

#define BATCH 2
#define H 512
#define W 512
#define NWORDS (W / 32)          // 16
#define INF_SQ 1e12f

// Row-pass output, packed: .x = dist^2 to nearest fg (mask==1) in the row,
//                          .y = dist^2 to nearest bg (mask==0) in the row.
__device__ float2 g_row[BATCH * H * W];

// Nearest set bit to position i in a 512-bit mask (16 words). Returns a huge
// value if no bit is set. Typical path: no word-escape loops taken.
__device__ __forceinline__ int nearest_set_bit(const uint32_t* __restrict__ m, int i) {
    const int wi = i >> 5, bi = i & 31;
    int dL = 1 << 20, dR = 1 << 20;

    const uint32_t below = m[wi] & (0xffffffffu >> (31 - bi));   // bits 0..bi
    if (below) {
        dL = bi - (31 - __clz(below));
    } else {
        for (int j = wi - 1; j >= 0; --j)
            if (m[j]) { dL = i - (j * 32 + 31 - __clz(m[j])); break; }
    }

    const uint32_t above = m[wi] & (0xffffffffu << bi);          // bits bi..31
    if (above) {
        dR = (__ffs(above) - 1) - bi;
    } else {
        for (int j = wi + 1; j < NWORDS; ++j)
            if (m[j]) { dR = j * 32 + (__ffs(m[j]) - 1) - i; break; }
    }

    return min(dL, dR);
}

// -------- Row pass: one block per row; ballot bitmask + O(1) bit search. ----
__global__ void __launch_bounds__(W) row_pass(const float* __restrict__ mask) {
    __shared__ uint32_t fgm[NWORDS];
    __shared__ uint32_t bgm[NWORDS];

    const int row = blockIdx.x;          // 0 .. BATCH*H-1
    const int i   = threadIdx.x;

    const bool isFg = (mask[row * W + i] == 1.0f);
    const uint32_t wm = __ballot_sync(0xffffffffu, isFg);
    if ((i & 31) == 0) {
        fgm[i >> 5] = wm;
        bgm[i >> 5] = ~wm;               // W==512 exactly fills 16 words
    }
    __syncthreads();

    const int dfg = nearest_set_bit(fgm, i);
    const int dbg = nearest_set_bit(bgm, i);

    const float fn = (dfg >= W) ? INF_SQ : (float)(dfg * dfg);
    const float fp = (dbg >= W) ? INF_SQ : (float)(dbg * dbg);
    g_row[row * W + i] = make_float2(fn, fp);
}

// -------- Column pass: one thread per output pixel, unroll-2 search. --------
// D[i] = min_k g[k] + (i-k)^2; outward search, early exit at o^2 >= best
// (exact since g >= 0). Edge clamp is exact (clamped candidate can't beat the
// true boundary candidate folded at o == i). The o+1 candidates are folded
// unconditionally: they are genuine candidates, so fminf is always safe.
#define CP_THREADS 256
__global__ void __launch_bounds__(CP_THREADS) col_pass(float* __restrict__ out) {
    const int idx = blockIdx.x * CP_THREADS + threadIdx.x;  // 0 .. BATCH*H*W-1
    const int c   = idx & (W - 1);
    const int t   = idx >> 9;            // W == 512
    const int i   = t & (H - 1);
    const int b   = t >> 9;              // H == 512

    const float2* __restrict__ g = g_row + b * H * W;

    const float2 own = g[i * W + c];
    float bn = own.x;
    float bp = own.y;

    #pragma unroll 1
    for (int o = 1; o < H; o += 2) {
        const float o2a = (float)(o * o);
        if (o2a >= bn && o2a >= bp) break;
        const float o2b = (float)((o + 1) * (o + 1));

        int ku0 = i - o;       ku0 = (ku0 < 0) ? 0 : ku0;
        int kd0 = i + o;       kd0 = (kd0 >= H) ? H - 1 : kd0;
        int ku1 = i - (o + 1); ku1 = (ku1 < 0) ? 0 : ku1;
        int kd1 = i + (o + 1); kd1 = (kd1 >= H) ? H - 1 : kd1;

        const float2 u0 = g[ku0 * W + c];
        const float2 d0 = g[kd0 * W + c];
        const float2 u1 = g[ku1 * W + c];
        const float2 d1 = g[kd1 * W + c];

        bn = fminf(bn, fminf(fminf(u0.x, d0.x) + o2a, fminf(u1.x, d1.x) + o2b));
        bp = fminf(bp, fminf(fminf(u0.y, d0.y) + o2a, fminf(u1.y, d1.y) + o2b));
    }

    out[idx] = sqrtf(bn) - sqrtf(bp);
}

extern "C" void kernel_launch(void* const* d_in, const int* in_sizes, int n_in,
                              void* d_out, int out_size) {
    const float* mask = (const float*)d_in[0];
    float* out = (float*)d_out;

    row_pass<<<BATCH * H, W>>>(mask);
    col_pass<<<(BATCH * H * W) / CP_THREADS, CP_THREADS>>>(out);
}